// round 1
// baseline (speedup 1.0000x reference)
#include <cuda_runtime.h>
#include <cstdint>

// Problem dims
#define B_    8
#define S_    2048
#define D_    768
#define M_TOT (B_ * S_)

static __device__ __constant__ float SCALE_INV = 0.036084391824351615f; // 1/sqrt(768)

// ---------------------------------------------------------------------------
// Scratch (static __device__ arrays — no allocation allowed in kernel_launch)
// ---------------------------------------------------------------------------
__device__ float g_Q[(size_t)M_TOT * D_];                 // 50.3 MB
__device__ float g_K[(size_t)M_TOT * D_];                 // 50.3 MB
__device__ float g_V[(size_t)M_TOT * D_];                 // 50.3 MB
__device__ float g_scores[(size_t)B_ * S_ * S_];          // 134 MB
__device__ float g_wbar[B_ * S_];                         // column-summed softmax weights

// ---------------------------------------------------------------------------
// GEMM tile config: C[128,128] per block, K-step 16, 256 threads, 8x8 micro
// Both operands are row-major with the contraction dim contiguous (stride 768):
//   C[m,n] = sum_k A[m*768+k] * B[n*768+k]
// ---------------------------------------------------------------------------
#define BM  128
#define BN  128
#define BK  16
#define PAD 4            // stride 132 floats: keeps 16B alignment for float4 LDS

__device__ __forceinline__ void gemm_tile(
    const float* __restrict__ A, const float* __restrict__ Bp,
    float (*As)[BM + PAD], float (*Bs)[BN + PAD],
    float acc[8][8], int tid, int tx, int ty)
{
    for (int k0 = 0; k0 < D_; k0 += BK) {
        // Load 128x16 tiles of A and B (512 float4 each, 2 per thread),
        // stored transposed (k-major) into shared memory.
#pragma unroll
        for (int l = 0; l < 2; l++) {
            int idx = tid + l * 256;
            int row = idx >> 2;
            int c4  = (idx & 3) * 4;
            float4 va = *(const float4*)(A + (size_t)row * D_ + k0 + c4);
            As[c4 + 0][row] = va.x; As[c4 + 1][row] = va.y;
            As[c4 + 2][row] = va.z; As[c4 + 3][row] = va.w;
            float4 vb = *(const float4*)(Bp + (size_t)row * D_ + k0 + c4);
            Bs[c4 + 0][row] = vb.x; Bs[c4 + 1][row] = vb.y;
            Bs[c4 + 2][row] = vb.z; Bs[c4 + 3][row] = vb.w;
        }
        __syncthreads();
#pragma unroll
        for (int k = 0; k < BK; k++) {
            float a[8], b[8];
            *(float4*)(a)     = *(const float4*)(&As[k][ty * 8]);
            *(float4*)(a + 4) = *(const float4*)(&As[k][ty * 8 + 4]);
            *(float4*)(b)     = *(const float4*)(&Bs[k][tx * 8]);
            *(float4*)(b + 4) = *(const float4*)(&Bs[k][tx * 8 + 4]);
#pragma unroll
            for (int i = 0; i < 8; i++)
#pragma unroll
                for (int j = 0; j < 8; j++)
                    acc[i][j] += a[i] * b[j];
        }
        __syncthreads();
    }
}

// ---------------------------------------------------------------------------
// Kernel 1: QKV projection.  grid (6, 128, 3), block 256.
//   z selects {Q,K,V}.  C[m,o] = sum_i X[m,i]*W[o,i] + b[o]
// ---------------------------------------------------------------------------
__global__ __launch_bounds__(256, 2) void qkv_kernel(
    const float* __restrict__ X,
    const float* __restrict__ Wq, const float* __restrict__ bq,
    const float* __restrict__ Wk, const float* __restrict__ bk,
    const float* __restrict__ Wv, const float* __restrict__ bv)
{
    __shared__ float As[BK][BM + PAD];
    __shared__ float Bs[BK][BN + PAD];

    const float* W; const float* bias; float* C;
    if (blockIdx.z == 0)      { W = Wq; bias = bq; C = g_Q; }
    else if (blockIdx.z == 1) { W = Wk; bias = bk; C = g_K; }
    else                      { W = Wv; bias = bv; C = g_V; }

    int tid = threadIdx.x, tx = tid & 15, ty = tid >> 4;
    int m0 = blockIdx.y * BM, n0 = blockIdx.x * BN;

    float acc[8][8] = {};
    gemm_tile(X + (size_t)m0 * D_, W + (size_t)n0 * D_, As, Bs, acc, tid, tx, ty);

#pragma unroll
    for (int i = 0; i < 8; i++) {
        int m = m0 + ty * 8 + i;
#pragma unroll
        for (int j = 0; j < 8; j += 4) {
            int n = n0 + tx * 8 + j;
            float4 bb = *(const float4*)(bias + n);
            float4 v;
            v.x = acc[i][j + 0] + bb.x;
            v.y = acc[i][j + 1] + bb.y;
            v.z = acc[i][j + 2] + bb.z;
            v.w = acc[i][j + 3] + bb.w;
            *(float4*)(C + (size_t)m * D_ + n) = v;
        }
    }
}

// ---------------------------------------------------------------------------
// Kernel 2: scores = Q @ K^T / sqrt(D), masked.  grid (16, 16, 8), block 256.
// ---------------------------------------------------------------------------
__global__ __launch_bounds__(256, 2) void scores_kernel(const int* __restrict__ mask)
{
    __shared__ float As[BK][BM + PAD];
    __shared__ float Bs[BK][BN + PAD];

    int b = blockIdx.z;
    int tid = threadIdx.x, tx = tid & 15, ty = tid >> 4;
    int q0 = blockIdx.y * BM, n0 = blockIdx.x * BN;

    float acc[8][8] = {};
    gemm_tile(g_Q + ((size_t)b * S_ + q0) * D_,
              g_K + ((size_t)b * S_ + n0) * D_, As, Bs, acc, tid, tx, ty);

    int mk[8];
#pragma unroll
    for (int j = 0; j < 8; j++) mk[j] = mask[b * S_ + n0 + tx * 8 + j];

    float* srow = g_scores + (size_t)b * S_ * S_;
#pragma unroll
    for (int i = 0; i < 8; i++) {
        int q = q0 + ty * 8 + i;
#pragma unroll
        for (int j = 0; j < 8; j += 4) {
            float4 v;
            v.x = mk[j + 0] ? acc[i][j + 0] * SCALE_INV : -1e30f;
            v.y = mk[j + 1] ? acc[i][j + 1] * SCALE_INV : -1e30f;
            v.z = mk[j + 2] ? acc[i][j + 2] * SCALE_INV : -1e30f;
            v.w = mk[j + 3] ? acc[i][j + 3] * SCALE_INV : -1e30f;
            *(float4*)(srow + (size_t)q * S_ + n0 + tx * 8 + j) = v;
        }
    }
}

// ---------------------------------------------------------------------------
// Kernel 3: per-row softmax + column sum.  grid (256, 8), block 256.
// Each warp owns one q-row (2048 scores, 64 per lane). Column sums are
// accumulated in shared, then added once per block to g_wbar (global atomics).
// ---------------------------------------------------------------------------
__global__ __launch_bounds__(256) void softmax_colsum_kernel()
{
    int b    = blockIdx.y;
    int q    = blockIdx.x * 8 + (threadIdx.x >> 5);
    int lane = threadIdx.x & 31;

    __shared__ float wsm[S_];
    for (int i = threadIdx.x; i < S_; i += 256) wsm[i] = 0.0f;
    __syncthreads();

    const float* row = g_scores + (size_t)b * S_ * S_ + (size_t)q * S_;

    float s[64];
    float m = -1e30f;
#pragma unroll
    for (int j = 0; j < 64; j++) {
        s[j] = row[lane + 32 * j];
        m = fmaxf(m, s[j]);
    }
#pragma unroll
    for (int o = 16; o; o >>= 1) m = fmaxf(m, __shfl_xor_sync(0xffffffffu, m, o));

    float z = 0.0f;
#pragma unroll
    for (int j = 0; j < 64; j++) {
        s[j] = __expf(s[j] - m);   // masked entries (-1e30) underflow to exactly 0
        z += s[j];
    }
#pragma unroll
    for (int o = 16; o; o >>= 1) z += __shfl_xor_sync(0xffffffffu, z, o);

    float rz = 1.0f / z;
#pragma unroll
    for (int j = 0; j < 64; j++) atomicAdd(&wsm[lane + 32 * j], s[j] * rz);
    __syncthreads();

    for (int i = threadIdx.x; i < S_; i += 256)
        atomicAdd(&g_wbar[b * S_ + i], wsm[i]);
}

// ---------------------------------------------------------------------------
// Kernel 4: out[b,:] = (1/S) * wbar[b,:] @ V[b].  grid (16, 8), block 256.
// Each block handles a 128-key chunk; partial results via global atomics.
// ---------------------------------------------------------------------------
__global__ __launch_bounds__(256) void final_gemv_kernel(float* __restrict__ out)
{
    int b  = blockIdx.y;
    int k0 = blockIdx.x * 128;

    __shared__ float wsm[128];
    if (threadIdx.x < 128) wsm[threadIdx.x] = g_wbar[b * S_ + k0 + threadIdx.x];
    __syncthreads();

    const float* V = g_V + ((size_t)b * S_ + k0) * D_;
    int o = threadIdx.x;
    float c0 = 0.0f, c1 = 0.0f, c2 = 0.0f;
#pragma unroll 4
    for (int k = 0; k < 128; k++) {
        float w = wsm[k];
        const float* vr = V + (size_t)k * D_;
        c0 += w * vr[o];
        c1 += w * vr[o + 256];
        c2 += w * vr[o + 512];
    }
    const float invS = 1.0f / (float)S_;
    atomicAdd(&out[b * D_ + o      ], c0 * invS);
    atomicAdd(&out[b * D_ + o + 256], c1 * invS);
    atomicAdd(&out[b * D_ + o + 512], c2 * invS);
}

// ---------------------------------------------------------------------------
// Kernel 0: zero the accumulators (wbar + out, out is poisoned by harness).
// ---------------------------------------------------------------------------
__global__ void zero_kernel(float* __restrict__ out)
{
    int i = blockIdx.x * 256 + threadIdx.x;
    if (i < B_ * S_) g_wbar[i] = 0.0f;
    if (i < B_ * D_) out[i]    = 0.0f;
}

// ---------------------------------------------------------------------------
// kernel_launch — graph-capturable: kernel launches only, no sync, no alloc.
// Input order per metadata: x, mask, Wq, bq, Wk, bk, Wv, bv
// ---------------------------------------------------------------------------
extern "C" void kernel_launch(void* const* d_in, const int* in_sizes, int n_in,
                              void* d_out, int out_size)
{
    const float* x    = (const float*)d_in[0];
    const int*   mask = (const int*)  d_in[1];
    const float* Wq   = (const float*)d_in[2];
    const float* bq   = (const float*)d_in[3];
    const float* Wk   = (const float*)d_in[4];
    const float* bk   = (const float*)d_in[5];
    const float* Wv   = (const float*)d_in[6];
    const float* bv   = (const float*)d_in[7];
    float* out = (float*)d_out;

    zero_kernel<<<64, 256>>>(out);
    qkv_kernel<<<dim3(D_ / BN, M_TOT / BM, 3), 256>>>(x, Wq, bq, Wk, bk, Wv, bv);
    scores_kernel<<<dim3(S_ / BN, S_ / BM, B_), 256>>>(mask);
    softmax_colsum_kernel<<<dim3(S_ / 8, B_), 256>>>();
    final_gemv_kernel<<<dim3(S_ / 128, B_), 256>>>(out);
}

// round 5
// speedup vs baseline: 1.5766x; 1.5766x over previous
#include <cuda_runtime.h>
#include <cuda_bf16.h>
#include <cstdint>

// Problem dims
#define B_    8
#define S_    2048
#define D_    768
#define M_TOT (B_ * S_)
#define W_ELEMS (D_ * D_)

static __device__ __constant__ float SCALE_INV = 0.036084391824351615f; // 1/sqrt(768)

// ---------------------------------------------------------------------------
// Scratch (__device__ globals — no allocation allowed)
// ---------------------------------------------------------------------------
__device__ __nv_bfloat16 g_xhi[(size_t)M_TOT * D_];
__device__ __nv_bfloat16 g_xlo[(size_t)M_TOT * D_];
__device__ __nv_bfloat16 g_Whi[3 * (size_t)W_ELEMS];
__device__ __nv_bfloat16 g_Wlo[3 * (size_t)W_ELEMS];
__device__ __nv_bfloat16 g_Qhi[(size_t)M_TOT * D_];
__device__ __nv_bfloat16 g_Qlo[(size_t)M_TOT * D_];
__device__ __nv_bfloat16 g_Khi[(size_t)M_TOT * D_];
__device__ __nv_bfloat16 g_Klo[(size_t)M_TOT * D_];
__device__ float         g_V[(size_t)M_TOT * D_];
__device__ float         g_scores[(size_t)B_ * S_ * S_];
__device__ float         g_wbar[B_ * S_];

// ---------------------------------------------------------------------------
// bf16 split helpers
// ---------------------------------------------------------------------------
__device__ __forceinline__ void split_bf16(float v, __nv_bfloat16& h, __nv_bfloat16& l)
{
    h = __float2bfloat16(v);
    l = __float2bfloat16(v - __bfloat162float(h));
}

// ---------------------------------------------------------------------------
// Kernel: split a fp32 tensor into bf16 hi/lo.  which: 0=x, 1..3 = Wq/Wk/Wv.
// ---------------------------------------------------------------------------
__global__ void convert_split_kernel(const float* __restrict__ src, int which, int n)
{
    __nv_bfloat16* hi; __nv_bfloat16* lo;
    if (which == 0) { hi = g_xhi; lo = g_xlo; }
    else {
        size_t off = (size_t)(which - 1) * W_ELEMS;
        hi = g_Whi + off; lo = g_Wlo + off;
    }
    int i = (blockIdx.x * 256 + threadIdx.x) * 4;
    if (i >= n) return;
    float4 v = *(const float4*)(src + i);
    float vv[4] = { v.x, v.y, v.z, v.w };
#pragma unroll
    for (int j = 0; j < 4; j++) {
        __nv_bfloat16 h, l;
        split_bf16(vv[j], h, l);
        hi[i + j] = h;
        lo[i + j] = l;
    }
}

// ---------------------------------------------------------------------------
// mma.sync bf16 GEMM machinery.
// Block: 256 thr = 8 warps (2x4), block tile 128x128, BK=32 (two k16 steps).
// Smem rows padded to stride 40 bf16 (80 B) -> conflict-free frag loads.
// A is [m][k] row-major, B is [n][k] row-major (both k contiguous) — which is
// exactly the mma .row.col operand pair.
// ---------------------------------------------------------------------------
#define BK  32
#define STR 40

struct SmemT {
    __nv_bfloat16 Ahi[128 * STR];
    __nv_bfloat16 Alo[128 * STR];
    __nv_bfloat16 Bhi[128 * STR];
    __nv_bfloat16 Blo[128 * STR];
};

__device__ __forceinline__ void mma_bf16(float* c,
    uint32_t a0, uint32_t a1, uint32_t a2, uint32_t a3, uint32_t b0, uint32_t b1)
{
    asm volatile(
        "mma.sync.aligned.m16n8k16.row.col.f32.bf16.bf16.f32 "
        "{%0,%1,%2,%3}, {%4,%5,%6,%7}, {%8,%9}, {%0,%1,%2,%3};"
        : "+f"(c[0]), "+f"(c[1]), "+f"(c[2]), "+f"(c[3])
        : "r"(a0), "r"(a1), "r"(a2), "r"(a3), "r"(b0), "r"(b1));
}

// A fragment: a0={A[g][c],A[g][c+1]} a1=rows+8, a2=cols+8, a3=both (+8)
__device__ __forceinline__ void lda(const __nv_bfloat16* As, int r0, int c0, uint32_t f[4])
{
    f[0] = *(const uint32_t*)(As + r0 * STR + c0);
    f[1] = *(const uint32_t*)(As + (r0 + 8) * STR + c0);
    f[2] = *(const uint32_t*)(As + r0 * STR + c0 + 8);
    f[3] = *(const uint32_t*)(As + (r0 + 8) * STR + c0 + 8);
}
// B fragment (B stored [n][k]): b0={B[k=c][n=r0],B[k=c+1][n=r0]}, b1=k+8
__device__ __forceinline__ void ldb(const __nv_bfloat16* Bs, int r0, int c0, uint32_t f[2])
{
    f[0] = *(const uint32_t*)(Bs + r0 * STR + c0);
    f[1] = *(const uint32_t*)(Bs + r0 * STR + c0 + 8);
}

// Split-bf16 mainloop: acc += Ah*Bh + Ah*Bl + Al*Bh over D_=768.
__device__ __forceinline__ void gemm_mainloop(
    const __nv_bfloat16* __restrict__ Ah, const __nv_bfloat16* __restrict__ Al,
    const __nv_bfloat16* __restrict__ Bh, const __nv_bfloat16* __restrict__ Bl,
    SmemT* sm, float acc[4][4][4], int tid)
{
    int lane = tid & 31, warp = tid >> 5;
    int wm = (warp >> 2) * 64, wn = (warp & 3) * 32;
    int g = lane >> 2, tc = lane & 3;
    int lrow = tid >> 2, lc8 = (tid & 3) * 8;

    for (int k0 = 0; k0 < D_; k0 += BK) {
        __syncthreads();
#pragma unroll
        for (int l = 0; l < 2; l++) {
            int row = lrow + l * 64;
            size_t go = (size_t)row * D_ + k0 + lc8;
            int so = row * STR + lc8;
            *(uint4*)(sm->Ahi + so) = *(const uint4*)(Ah + go);
            *(uint4*)(sm->Alo + so) = *(const uint4*)(Al + go);
            *(uint4*)(sm->Bhi + so) = *(const uint4*)(Bh + go);
            *(uint4*)(sm->Blo + so) = *(const uint4*)(Bl + go);
        }
        __syncthreads();
#pragma unroll
        for (int ks = 0; ks < BK; ks += 16) {
            int ac = ks + tc * 2;
            uint32_t ah[4][4], al[4][4];
#pragma unroll
            for (int mt = 0; mt < 4; mt++) {
                lda(sm->Ahi, wm + mt * 16 + g, ac, ah[mt]);
                lda(sm->Alo, wm + mt * 16 + g, ac, al[mt]);
            }
#pragma unroll
            for (int nt = 0; nt < 4; nt++) {
                uint32_t bh[2], bl[2];
                ldb(sm->Bhi, wn + nt * 8 + g, ac, bh);
                ldb(sm->Blo, wn + nt * 8 + g, ac, bl);
#pragma unroll
                for (int mt = 0; mt < 4; mt++) {
                    mma_bf16(acc[mt][nt], ah[mt][0], ah[mt][1], ah[mt][2], ah[mt][3], bh[0], bh[1]);
                    mma_bf16(acc[mt][nt], ah[mt][0], ah[mt][1], ah[mt][2], ah[mt][3], bl[0], bl[1]);
                    mma_bf16(acc[mt][nt], al[mt][0], al[mt][1], al[mt][2], al[mt][3], bh[0], bh[1]);
                }
            }
        }
    }
}

// ---------------------------------------------------------------------------
// Kernel 1: QKV projection.  grid (6, 128, 3), block 256.
// z=0 -> Q (split bf16 out), z=1 -> K (split bf16 out), z=2 -> V (fp32 out).
// ---------------------------------------------------------------------------
__global__ __launch_bounds__(256, 1) void qkv_mma_kernel(
    const float* __restrict__ bq, const float* __restrict__ bk, const float* __restrict__ bv)
{
    __shared__ SmemT sm;
    int z = blockIdx.z;
    int m_blk = blockIdx.y * 128, n_blk = blockIdx.x * 128;

    const __nv_bfloat16* Bh = g_Whi + (size_t)z * W_ELEMS + (size_t)n_blk * D_;
    const __nv_bfloat16* Bl = g_Wlo + (size_t)z * W_ELEMS + (size_t)n_blk * D_;
    const float* bias = (z == 0) ? bq : (z == 1) ? bk : bv;

    float acc[4][4][4] = {};
    gemm_mainloop(g_xhi + (size_t)m_blk * D_, g_xlo + (size_t)m_blk * D_,
                  Bh, Bl, &sm, acc, threadIdx.x);

    int lane = threadIdx.x & 31, warp = threadIdx.x >> 5;
    int wm = (warp >> 2) * 64, wn = (warp & 3) * 32;
    int g = lane >> 2, tc = lane & 3;

    __nv_bfloat16* Oh = (z == 0) ? g_Qhi : g_Khi;
    __nv_bfloat16* Ol = (z == 0) ? g_Qlo : g_Klo;

#pragma unroll
    for (int mt = 0; mt < 4; mt++) {
#pragma unroll
        for (int nt = 0; nt < 4; nt++) {
            int n = n_blk + wn + nt * 8 + tc * 2;
            float2 bb = *(const float2*)(bias + n);
            int m0 = m_blk + wm + mt * 16 + g;
            float r00 = acc[mt][nt][0] + bb.x, r01 = acc[mt][nt][1] + bb.y;
            float r10 = acc[mt][nt][2] + bb.x, r11 = acc[mt][nt][3] + bb.y;
            if (z == 2) {
                *(float2*)(g_V + (size_t)m0 * D_ + n)       = make_float2(r00, r01);
                *(float2*)(g_V + (size_t)(m0 + 8) * D_ + n) = make_float2(r10, r11);
            } else {
                size_t o0 = (size_t)m0 * D_ + n;
                size_t o1 = (size_t)(m0 + 8) * D_ + n;
                __nv_bfloat16 h, l;
                split_bf16(r00, h, l); Oh[o0]     = h; Ol[o0]     = l;
                split_bf16(r01, h, l); Oh[o0 + 1] = h; Ol[o0 + 1] = l;
                split_bf16(r10, h, l); Oh[o1]     = h; Ol[o1]     = l;
                split_bf16(r11, h, l); Oh[o1 + 1] = h; Ol[o1 + 1] = l;
            }
        }
    }
}

// ---------------------------------------------------------------------------
// Kernel 2: scores = Q K^T * SCALE_INV, masked.  grid (16, 16, 8), block 256.
// ---------------------------------------------------------------------------
__global__ __launch_bounds__(256, 1) void scores_mma_kernel(const int* __restrict__ mask)
{
    __shared__ SmemT sm;
    int b = blockIdx.z;
    int m_blk = blockIdx.y * 128, n_blk = blockIdx.x * 128;
    size_t abase = ((size_t)b * S_ + m_blk) * D_;
    size_t bbase = ((size_t)b * S_ + n_blk) * D_;

    float acc[4][4][4] = {};
    gemm_mainloop(g_Qhi + abase, g_Qlo + abase, g_Khi + bbase, g_Klo + bbase,
                  &sm, acc, threadIdx.x);

    int lane = threadIdx.x & 31, warp = threadIdx.x >> 5;
    int wm = (warp >> 2) * 64, wn = (warp & 3) * 32;
    int g = lane >> 2, tc = lane & 3;

    float* srow = g_scores + (size_t)b * S_ * S_;
#pragma unroll
    for (int mt = 0; mt < 4; mt++) {
#pragma unroll
        for (int nt = 0; nt < 4; nt++) {
            int n = n_blk + wn + nt * 8 + tc * 2;
            int2 mk = *(const int2*)(mask + b * S_ + n);
            int m0 = m_blk + wm + mt * 16 + g;
            float s00 = mk.x ? acc[mt][nt][0] * SCALE_INV : -1e30f;
            float s01 = mk.y ? acc[mt][nt][1] * SCALE_INV : -1e30f;
            float s10 = mk.x ? acc[mt][nt][2] * SCALE_INV : -1e30f;
            float s11 = mk.y ? acc[mt][nt][3] * SCALE_INV : -1e30f;
            *(float2*)(srow + (size_t)m0 * S_ + n)       = make_float2(s00, s01);
            *(float2*)(srow + (size_t)(m0 + 8) * S_ + n) = make_float2(s10, s11);
        }
    }
}

// ---------------------------------------------------------------------------
// Kernel 3: per-row softmax + column sum.  grid (256, 8), block 256.
// ---------------------------------------------------------------------------
__global__ __launch_bounds__(256) void softmax_colsum_kernel()
{
    int b    = blockIdx.y;
    int q    = blockIdx.x * 8 + (threadIdx.x >> 5);
    int lane = threadIdx.x & 31;

    __shared__ float wsm[S_];
    for (int i = threadIdx.x; i < S_; i += 256) wsm[i] = 0.0f;
    __syncthreads();

    const float* row = g_scores + (size_t)b * S_ * S_ + (size_t)q * S_;

    float s[64];
    float m = -1e30f;
#pragma unroll
    for (int j = 0; j < 64; j++) {
        s[j] = row[lane + 32 * j];
        m = fmaxf(m, s[j]);
    }
#pragma unroll
    for (int o = 16; o; o >>= 1) m = fmaxf(m, __shfl_xor_sync(0xffffffffu, m, o));

    float z = 0.0f;
#pragma unroll
    for (int j = 0; j < 64; j++) {
        s[j] = __expf(s[j] - m);   // masked entries (-1e30) underflow to exactly 0
        z += s[j];
    }
#pragma unroll
    for (int o = 16; o; o >>= 1) z += __shfl_xor_sync(0xffffffffu, z, o);

    float rz = 1.0f / z;
#pragma unroll
    for (int j = 0; j < 64; j++) atomicAdd(&wsm[lane + 32 * j], s[j] * rz);
    __syncthreads();

    for (int i = threadIdx.x; i < S_; i += 256)
        atomicAdd(&g_wbar[b * S_ + i], wsm[i]);
}

// ---------------------------------------------------------------------------
// Kernel 4: out[b,:] = (1/S) * wbar[b,:] @ V[b].  grid (16, 8), block 256.
// ---------------------------------------------------------------------------
__global__ __launch_bounds__(256) void final_gemv_kernel(float* __restrict__ out)
{
    int b  = blockIdx.y;
    int k0 = blockIdx.x * 128;

    __shared__ float wsm[128];
    if (threadIdx.x < 128) wsm[threadIdx.x] = g_wbar[b * S_ + k0 + threadIdx.x];
    __syncthreads();

    const float* V = g_V + ((size_t)b * S_ + k0) * D_;
    int o = threadIdx.x;
    float c0 = 0.0f, c1 = 0.0f, c2 = 0.0f;
#pragma unroll 4
    for (int k = 0; k < 128; k++) {
        float w = wsm[k];
        const float* vr = V + (size_t)k * D_;
        c0 += w * vr[o];
        c1 += w * vr[o + 256];
        c2 += w * vr[o + 512];
    }
    const float invS = 1.0f / (float)S_;
    atomicAdd(&out[b * D_ + o      ], c0 * invS);
    atomicAdd(&out[b * D_ + o + 256], c1 * invS);
    atomicAdd(&out[b * D_ + o + 512], c2 * invS);
}

// ---------------------------------------------------------------------------
// Kernel 0: zero the accumulators (wbar + out).
// ---------------------------------------------------------------------------
__global__ void zero_kernel(float* __restrict__ out)
{
    int i = blockIdx.x * 256 + threadIdx.x;
    if (i < B_ * S_) g_wbar[i] = 0.0f;
    if (i < B_ * D_) out[i]    = 0.0f;
}

// ---------------------------------------------------------------------------
// kernel_launch — graph-capturable: kernel launches only.
// Input order: x, mask, Wq, bq, Wk, bk, Wv, bv
// ---------------------------------------------------------------------------
extern "C" void kernel_launch(void* const* d_in, const int* in_sizes, int n_in,
                              void* d_out, int out_size)
{
    const float* x    = (const float*)d_in[0];
    const int*   mask = (const int*)  d_in[1];
    const float* Wq   = (const float*)d_in[2];
    const float* bq   = (const float*)d_in[3];
    const float* Wk   = (const float*)d_in[4];
    const float* bk   = (const float*)d_in[5];
    const float* Wv   = (const float*)d_in[6];
    const float* bv   = (const float*)d_in[7];
    float* out = (float*)d_out;

    zero_kernel<<<64, 256>>>(out);

    int nx = M_TOT * D_;
    convert_split_kernel<<<(nx / 4 + 255) / 256, 256>>>(x, 0, nx);
    convert_split_kernel<<<(W_ELEMS / 4 + 255) / 256, 256>>>(Wq, 1, W_ELEMS);
    convert_split_kernel<<<(W_ELEMS / 4 + 255) / 256, 256>>>(Wk, 2, W_ELEMS);
    convert_split_kernel<<<(W_ELEMS / 4 + 255) / 256, 256>>>(Wv, 3, W_ELEMS);

    qkv_mma_kernel<<<dim3(D_ / 128, M_TOT / 128, 3), 256>>>(bq, bk, bv);
    scores_mma_kernel<<<dim3(S_ / 128, S_ / 128, B_), 256>>>(mask);
    softmax_colsum_kernel<<<dim3(S_ / 8, B_), 256>>>();
    final_gemv_kernel<<<dim3(S_ / 128, B_), 256>>>(out);
}

// round 9
// speedup vs baseline: 1.6460x; 1.0440x over previous
#include <cuda_runtime.h>
#include <cuda_bf16.h>
#include <cstdint>

// Problem dims
#define B_    8
#define S_    2048
#define D_    768
#define M_TOT (B_ * S_)
#define W_ELEMS (D_ * D_)

static __device__ __constant__ float SCALE_INV = 0.036084391824351615f; // 1/sqrt(768)

// ---------------------------------------------------------------------------
// Scratch (__device__ globals — no allocation allowed)
// ---------------------------------------------------------------------------
__device__ __nv_bfloat16 g_xhi[(size_t)M_TOT * D_];
__device__ __nv_bfloat16 g_xlo[(size_t)M_TOT * D_];
__device__ __nv_bfloat16 g_Whi[3 * (size_t)W_ELEMS];
__device__ __nv_bfloat16 g_Wlo[3 * (size_t)W_ELEMS];
__device__ __nv_bfloat16 g_Qhi[(size_t)M_TOT * D_];
__device__ __nv_bfloat16 g_Qlo[(size_t)M_TOT * D_];
__device__ __nv_bfloat16 g_Khi[(size_t)M_TOT * D_];
__device__ __nv_bfloat16 g_Klo[(size_t)M_TOT * D_];
__device__ float         g_V[(size_t)M_TOT * D_];
__device__ float         g_scores[(size_t)B_ * S_ * S_];
__device__ float         g_wbar[B_ * S_];

// ---------------------------------------------------------------------------
// GEMM config: block tile 128x128, BK=32, 8 warps (2x4), warp tile 64x32.
// Split-bf16 (3 MMA terms: AhBh + AhBl + AlBh), fp32 accumulate.
// Double-buffered cp.async stages; ldmatrix fragment loads.
// Smem pitch STR=40 bf16 (80B): ldmatrix 16B-bank indices 5i mod 8 -> no conflicts.
// ---------------------------------------------------------------------------
#define BK     32
#define NCHUNK (D_ / BK)          // 24
#define STR    40
#define ARR_B  (128 * STR * 2)    // 10240 bytes per array
#define STG_AH 0
#define STG_AL (1 * ARR_B)
#define STG_BH (2 * ARR_B)
#define STG_BL (3 * ARR_B)
#define STAGE_B (4 * ARR_B)       // 40960
#define SMEM_TOTAL (2 * STAGE_B)  // 81920

__device__ __forceinline__ uint32_t smem_u32(const void* p)
{
    uint32_t a;
    asm("{ .reg .u64 t; cvta.to.shared.u64 t, %1; cvt.u32.u64 %0, t; }" : "=r"(a) : "l"(p));
    return a;
}

#define CP_ASYNC16(saddr, gptr) \
    asm volatile("cp.async.cg.shared.global [%0], [%1], 16;" :: "r"(saddr), "l"(gptr))
#define CP_COMMIT()  asm volatile("cp.async.commit_group;" ::: "memory")
#define CP_WAIT1()   asm volatile("cp.async.wait_group 1;" ::: "memory")
#define CP_WAIT0()   asm volatile("cp.async.wait_group 0;" ::: "memory")

#define LDSM_X4(f, addr) \
    asm volatile("ldmatrix.sync.aligned.m8n8.x4.shared.b16 {%0,%1,%2,%3}, [%4];" \
        : "=r"((f)[0]), "=r"((f)[1]), "=r"((f)[2]), "=r"((f)[3]) : "r"(addr))

__device__ __forceinline__ void mma_bf16(float* c,
    uint32_t a0, uint32_t a1, uint32_t a2, uint32_t a3, uint32_t b0, uint32_t b1)
{
    asm volatile(
        "mma.sync.aligned.m16n8k16.row.col.f32.bf16.bf16.f32 "
        "{%0,%1,%2,%3}, {%4,%5,%6,%7}, {%8,%9}, {%0,%1,%2,%3};"
        : "+f"(c[0]), "+f"(c[1]), "+f"(c[2]), "+f"(c[3])
        : "r"(a0), "r"(a1), "r"(a2), "r"(a3), "r"(b0), "r"(b1));
}

// Issue cp.async for one 32-k chunk of all 4 arrays into stage `st`.
__device__ __forceinline__ void stage_async(uint32_t st,
    const __nv_bfloat16* __restrict__ Ah, const __nv_bfloat16* __restrict__ Al,
    const __nv_bfloat16* __restrict__ Bh, const __nv_bfloat16* __restrict__ Bl,
    int k0, int tid)
{
#pragma unroll
    for (int l = 0; l < 2; l++) {
        int idx = tid + l * 256;
        int row = idx & 127;
        int seg = idx >> 7;                       // 0..3 (16B segments of 64B row)
        size_t g = (size_t)row * D_ + k0 + seg * 8;
        uint32_t so = row * (STR * 2) + seg * 16;
        CP_ASYNC16(st + STG_AH + so, Ah + g);
        CP_ASYNC16(st + STG_AL + so, Al + g);
        CP_ASYNC16(st + STG_BH + so, Bh + g);
        CP_ASYNC16(st + STG_BL + so, Bl + g);
    }
}

// Pipelined mainloop. acc[mt][nt][4]; warp tile m=wm..wm+63, n=wn..wn+31.
__device__ __forceinline__ void gemm_mainloop(uint32_t sb,
    const __nv_bfloat16* __restrict__ Ah, const __nv_bfloat16* __restrict__ Al,
    const __nv_bfloat16* __restrict__ Bh, const __nv_bfloat16* __restrict__ Bl,
    float acc[4][4][4], int tid)
{
    int lane = tid & 31, warp = tid >> 5;
    int wm = (warp >> 2) * 64, wn = (warp & 3) * 32;

    // ldmatrix per-lane byte offsets
    int a_lr = (lane & 7) | (((lane >> 3) & 1) << 3);   // row 0..15
    int a_lc = (lane >> 4) * 8;                         // col 0/8
    uint32_t a_off = (uint32_t)(a_lr * STR + a_lc) * 2;
    int b_lr = (lane & 7) | ((lane >> 4) << 3);
    int b_lc = ((lane >> 3) & 1) * 8;
    uint32_t b_off = (uint32_t)(b_lr * STR + b_lc) * 2;

    uint32_t a_base = (uint32_t)(wm * STR) * 2 + a_off;     // + STG_AH/AL + stage
    uint32_t b_base = (uint32_t)(wn * STR) * 2 + b_off;

    stage_async(sb, Ah, Al, Bh, Bl, 0, tid);
    CP_COMMIT();

    for (int c = 0; c < NCHUNK; c++) {
        uint32_t st = sb + (uint32_t)(c & 1) * STAGE_B;
        if (c + 1 < NCHUNK) {
            stage_async(sb + (uint32_t)((c + 1) & 1) * STAGE_B, Ah, Al, Bh, Bl,
                        (c + 1) * BK, tid);
            CP_COMMIT();
            CP_WAIT1();
        } else {
            CP_WAIT0();
        }
        __syncthreads();

#pragma unroll
        for (int ks = 0; ks < 2; ks++) {
            uint32_t kb = ks * 32;                      // 16 bf16 = 32 bytes
            uint32_t ah[4][4], al[4][4];
#pragma unroll
            for (int mt = 0; mt < 4; mt++) {
                uint32_t ao = st + a_base + (uint32_t)(mt * 16 * STR) * 2 + kb;
                LDSM_X4(ah[mt], ao + STG_AH);
                LDSM_X4(al[mt], ao + STG_AL);
            }
#pragma unroll
            for (int ntp = 0; ntp < 2; ntp++) {
                uint32_t bo = st + b_base + (uint32_t)(ntp * 16 * STR) * 2 + kb;
                uint32_t bh[4], bl[4];
                LDSM_X4(bh, bo + STG_BH);
                LDSM_X4(bl, bo + STG_BL);
#pragma unroll
                for (int mt = 0; mt < 4; mt++) {
                    float* c0 = acc[mt][2 * ntp];
                    float* c1 = acc[mt][2 * ntp + 1];
                    mma_bf16(c0, ah[mt][0], ah[mt][1], ah[mt][2], ah[mt][3], bh[0], bh[1]);
                    mma_bf16(c0, ah[mt][0], ah[mt][1], ah[mt][2], ah[mt][3], bl[0], bl[1]);
                    mma_bf16(c0, al[mt][0], al[mt][1], al[mt][2], al[mt][3], bh[0], bh[1]);
                    mma_bf16(c1, ah[mt][0], ah[mt][1], ah[mt][2], ah[mt][3], bh[2], bh[3]);
                    mma_bf16(c1, ah[mt][0], ah[mt][1], ah[mt][2], ah[mt][3], bl[2], bl[3]);
                    mma_bf16(c1, al[mt][0], al[mt][1], al[mt][2], al[mt][3], bh[2], bh[3]);
                }
            }
        }
        __syncthreads();
    }
}

// ---------------------------------------------------------------------------
// bf16 split helpers
// ---------------------------------------------------------------------------
__device__ __forceinline__ void split_bf16(float v, __nv_bfloat16& h, __nv_bfloat16& l)
{
    h = __float2bfloat16(v);
    l = __float2bfloat16(v - __bfloat162float(h));
}

// ---------------------------------------------------------------------------
// Kernel: split fp32 -> bf16 hi/lo.  which: 0=x, 1..3 = Wq/Wk/Wv.
// ---------------------------------------------------------------------------
__global__ void convert_split_kernel(const float* __restrict__ src, int which, int n)
{
    __nv_bfloat16* hi; __nv_bfloat16* lo;
    if (which == 0) { hi = g_xhi; lo = g_xlo; }
    else { size_t off = (size_t)(which - 1) * W_ELEMS; hi = g_Whi + off; lo = g_Wlo + off; }
    int i = (blockIdx.x * 256 + threadIdx.x) * 4;
    if (i >= n) return;
    float4 v = *(const float4*)(src + i);
    float vv[4] = { v.x, v.y, v.z, v.w };
#pragma unroll
    for (int j = 0; j < 4; j++) {
        __nv_bfloat16 h, l;
        split_bf16(vv[j], h, l);
        hi[i + j] = h; lo[i + j] = l;
    }
}

// ---------------------------------------------------------------------------
// Kernel 1: QKV projection.  grid (6, 128, 3), block 256.
// z=0/1 -> Q/K (split bf16 out), z=2 -> V (fp32 out).
// ---------------------------------------------------------------------------
__global__ __launch_bounds__(256, 2) void qkv_mma_kernel(
    const float* __restrict__ bq, const float* __restrict__ bk, const float* __restrict__ bv)
{
    extern __shared__ char smem[];
    uint32_t sb = smem_u32(smem);
    int z = blockIdx.z;
    int m_blk = blockIdx.y * 128, n_blk = blockIdx.x * 128;

    const __nv_bfloat16* Bh = g_Whi + (size_t)z * W_ELEMS + (size_t)n_blk * D_;
    const __nv_bfloat16* Bl = g_Wlo + (size_t)z * W_ELEMS + (size_t)n_blk * D_;
    const float* bias = (z == 0) ? bq : (z == 1) ? bk : bv;

    float acc[4][4][4] = {};
    gemm_mainloop(sb, g_xhi + (size_t)m_blk * D_, g_xlo + (size_t)m_blk * D_,
                  Bh, Bl, acc, threadIdx.x);

    int lane = threadIdx.x & 31, warp = threadIdx.x >> 5;
    int wm = (warp >> 2) * 64, wn = (warp & 3) * 32;
    int g = lane >> 2, tc = lane & 3;

    __nv_bfloat16* Oh = (z == 0) ? g_Qhi : g_Khi;
    __nv_bfloat16* Ol = (z == 0) ? g_Qlo : g_Klo;

#pragma unroll
    for (int mt = 0; mt < 4; mt++) {
#pragma unroll
        for (int nt = 0; nt < 4; nt++) {
            int n = n_blk + wn + nt * 8 + tc * 2;
            float2 bb = *(const float2*)(bias + n);
            int m0 = m_blk + wm + mt * 16 + g;
            float r00 = acc[mt][nt][0] + bb.x, r01 = acc[mt][nt][1] + bb.y;
            float r10 = acc[mt][nt][2] + bb.x, r11 = acc[mt][nt][3] + bb.y;
            if (z == 2) {
                *(float2*)(g_V + (size_t)m0 * D_ + n)       = make_float2(r00, r01);
                *(float2*)(g_V + (size_t)(m0 + 8) * D_ + n) = make_float2(r10, r11);
            } else {
                size_t o0 = (size_t)m0 * D_ + n;
                size_t o1 = (size_t)(m0 + 8) * D_ + n;
                __nv_bfloat16 h, l;
                split_bf16(r00, h, l); Oh[o0]     = h; Ol[o0]     = l;
                split_bf16(r01, h, l); Oh[o0 + 1] = h; Ol[o0 + 1] = l;
                split_bf16(r10, h, l); Oh[o1]     = h; Ol[o1]     = l;
                split_bf16(r11, h, l); Oh[o1 + 1] = h; Ol[o1 + 1] = l;
            }
        }
    }
}

// ---------------------------------------------------------------------------
// Kernel 2: scores = Q K^T * SCALE_INV, masked.  grid (16, 16, 8), block 256.
// ---------------------------------------------------------------------------
__global__ __launch_bounds__(256, 2) void scores_mma_kernel(const int* __restrict__ mask)
{
    extern __shared__ char smem[];
    uint32_t sb = smem_u32(smem);
    int b = blockIdx.z;
    int m_blk = blockIdx.y * 128, n_blk = blockIdx.x * 128;
    size_t abase = ((size_t)b * S_ + m_blk) * D_;
    size_t bbase = ((size_t)b * S_ + n_blk) * D_;

    float acc[4][4][4] = {};
    gemm_mainloop(sb, g_Qhi + abase, g_Qlo + abase, g_Khi + bbase, g_Klo + bbase,
                  acc, threadIdx.x);

    int lane = threadIdx.x & 31, warp = threadIdx.x >> 5;
    int wm = (warp >> 2) * 64, wn = (warp & 3) * 32;
    int g = lane >> 2, tc = lane & 3;

    float* srow = g_scores + (size_t)b * S_ * S_;
#pragma unroll
    for (int mt = 0; mt < 4; mt++) {
#pragma unroll
        for (int nt = 0; nt < 4; nt++) {
            int n = n_blk + wn + nt * 8 + tc * 2;
            int2 mk = *(const int2*)(mask + b * S_ + n);
            int m0 = m_blk + wm + mt * 16 + g;
            float s00 = mk.x ? acc[mt][nt][0] * SCALE_INV : -1e30f;
            float s01 = mk.y ? acc[mt][nt][1] * SCALE_INV : -1e30f;
            float s10 = mk.x ? acc[mt][nt][2] * SCALE_INV : -1e30f;
            float s11 = mk.y ? acc[mt][nt][3] * SCALE_INV : -1e30f;
            *(float2*)(srow + (size_t)m0 * S_ + n)       = make_float2(s00, s01);
            *(float2*)(srow + (size_t)(m0 + 8) * S_ + n) = make_float2(s10, s11);
        }
    }
}

// ---------------------------------------------------------------------------
// Kernel 3: per-row softmax + column sum.  grid (256, 8), block 256.
// ---------------------------------------------------------------------------
__global__ __launch_bounds__(256) void softmax_colsum_kernel()
{
    int b    = blockIdx.y;
    int q    = blockIdx.x * 8 + (threadIdx.x >> 5);
    int lane = threadIdx.x & 31;

    __shared__ float wsm[S_];
    for (int i = threadIdx.x; i < S_; i += 256) wsm[i] = 0.0f;
    __syncthreads();

    const float* row = g_scores + (size_t)b * S_ * S_ + (size_t)q * S_;

    float s[64];
    float m = -1e30f;
#pragma unroll
    for (int j = 0; j < 64; j++) {
        s[j] = row[lane + 32 * j];
        m = fmaxf(m, s[j]);
    }
#pragma unroll
    for (int o = 16; o; o >>= 1) m = fmaxf(m, __shfl_xor_sync(0xffffffffu, m, o));

    float z = 0.0f;
#pragma unroll
    for (int j = 0; j < 64; j++) {
        s[j] = __expf(s[j] - m);
        z += s[j];
    }
#pragma unroll
    for (int o = 16; o; o >>= 1) z += __shfl_xor_sync(0xffffffffu, z, o);

    float rz = 1.0f / z;
#pragma unroll
    for (int j = 0; j < 64; j++) atomicAdd(&wsm[lane + 32 * j], s[j] * rz);
    __syncthreads();

    for (int i = threadIdx.x; i < S_; i += 256)
        atomicAdd(&g_wbar[b * S_ + i], wsm[i]);
}

// ---------------------------------------------------------------------------
// Kernel 4: out[b,:] = (1/S) * wbar[b,:] @ V[b].  grid (16, 8), block 256.
// ---------------------------------------------------------------------------
__global__ __launch_bounds__(256) void final_gemv_kernel(float* __restrict__ out)
{
    int b  = blockIdx.y;
    int k0 = blockIdx.x * 128;

    __shared__ float wsm[128];
    if (threadIdx.x < 128) wsm[threadIdx.x] = g_wbar[b * S_ + k0 + threadIdx.x];
    __syncthreads();

    const float* V = g_V + ((size_t)b * S_ + k0) * D_;
    int o = threadIdx.x;
    float c0 = 0.0f, c1 = 0.0f, c2 = 0.0f;
#pragma unroll 4
    for (int k = 0; k < 128; k++) {
        float w = wsm[k];
        const float* vr = V + (size_t)k * D_;
        c0 += w * vr[o];
        c1 += w * vr[o + 256];
        c2 += w * vr[o + 512];
    }
    const float invS = 1.0f / (float)S_;
    atomicAdd(&out[b * D_ + o      ], c0 * invS);
    atomicAdd(&out[b * D_ + o + 256], c1 * invS);
    atomicAdd(&out[b * D_ + o + 512], c2 * invS);
}

// ---------------------------------------------------------------------------
// Kernel 0: zero the accumulators.
// ---------------------------------------------------------------------------
__global__ void zero_kernel(float* __restrict__ out)
{
    int i = blockIdx.x * 256 + threadIdx.x;
    if (i < B_ * S_) g_wbar[i] = 0.0f;
    if (i < B_ * D_) out[i]    = 0.0f;
}

// ---------------------------------------------------------------------------
// kernel_launch — graph-capturable: kernel launches + idempotent attr set.
// Input order: x, mask, Wq, bq, Wk, bk, Wv, bv
// ---------------------------------------------------------------------------
extern "C" void kernel_launch(void* const* d_in, const int* in_sizes, int n_in,
                              void* d_out, int out_size)
{
    const float* x    = (const float*)d_in[0];
    const int*   mask = (const int*)  d_in[1];
    const float* Wq   = (const float*)d_in[2];
    const float* bq   = (const float*)d_in[3];
    const float* Wk   = (const float*)d_in[4];
    const float* bk   = (const float*)d_in[5];
    const float* Wv   = (const float*)d_in[6];
    const float* bv   = (const float*)d_in[7];
    float* out = (float*)d_out;

    cudaFuncSetAttribute(qkv_mma_kernel,    cudaFuncAttributeMaxDynamicSharedMemorySize, SMEM_TOTAL);
    cudaFuncSetAttribute(scores_mma_kernel, cudaFuncAttributeMaxDynamicSharedMemorySize, SMEM_TOTAL);

    zero_kernel<<<64, 256>>>(out);

    int nx = M_TOT * D_;
    convert_split_kernel<<<(nx / 4 + 255) / 256, 256>>>(x, 0, nx);
    convert_split_kernel<<<(W_ELEMS / 4 + 255) / 256, 256>>>(Wq, 1, W_ELEMS);
    convert_split_kernel<<<(W_ELEMS / 4 + 255) / 256, 256>>>(Wk, 2, W_ELEMS);
    convert_split_kernel<<<(W_ELEMS / 4 + 255) / 256, 256>>>(Wv, 3, W_ELEMS);

    qkv_mma_kernel<<<dim3(D_ / 128, M_TOT / 128, 3), 256, SMEM_TOTAL>>>(bq, bk, bv);
    scores_mma_kernel<<<dim3(S_ / 128, S_ / 128, B_), 256, SMEM_TOTAL>>>(mask);
    softmax_colsum_kernel<<<dim3(S_ / 8, B_), 256>>>();
    final_gemv_kernel<<<dim3(S_ / 128, B_), 256>>>(out);
}